// round 10
// baseline (speedup 1.0000x reference)
#include <cuda_runtime.h>
#include <math.h>
#include <stdint.h>

#define NN   256
#define TT   16383
#define BB   8
#define LL   2097152
#define FF   129
#define TILE 64
#define NTHR 512
#define NBLK ((TT + TILE - 1) / TILE)   // 256

#define BFT ((size_t)BB * FF * TT)
#define BNT ((size_t)BB * NN * TT)
#define O_SPEC  ((size_t)0)
#define O_STFT  (BFT)
#define O_REAL  (BFT + BNT)
#define O_IMAG  (BFT + 2*BNT)
#define O_PHASE (BFT + 3*BNT)

// Replica coeff table padded to 144 rows (f=129..143 dummy, read-safe).
#define CROWS 144
__device__ float2 g_coeff[CROWS * NN];   // 294 KB

__device__ __forceinline__ unsigned long long pk2(float x, float y) {
    unsigned long long r;
    asm("mov.b64 %0, {%1,%2};" : "=l"(r) : "f"(x), "f"(y));
    return r;
}
__device__ __forceinline__ void upk2(unsigned long long v, float& x, float& y) {
    asm("mov.b64 {%0,%1}, %2;" : "=f"(x), "=f"(y) : "l"(v));
}
__device__ __forceinline__ void fma2(unsigned long long& d,
                                     unsigned long long a, unsigned long long b) {
    asm("fma.rn.f32x2 %0, %1, %2, %0;" : "+l"(d) : "l"(a), "l"(b));
}

// Replica of reference coeff: exp((-2i*pi/256)*(f*n)); angle = fl32(c32*(f*n)),
// cos/sin via libdevice cosf/sinf (bit-identical to XLA:GPU's jnp.exp lowering).
__global__ void build_coeff() {
    int idx = blockIdx.x * 256 + threadIdx.x;
    if (idx >= CROWS * NN) return;
    int f = idx >> 8, n = idx & 255;
    const float c32 = (float)(-2.0 * M_PI / 256.0);
    float m  = (float)(f * n);
    float th = __fmul_rn(c32, m);
    g_coeff[idx] = make_float2(cosf(th), sinf(th));
}

__global__ __launch_bounds__(NTHR, 1)
void dstft_main(const float* __restrict__ x,
                const float* __restrict__ wlp,
                const float* __restrict__ stp,
                const float* __restrict__ pwp,
                float* __restrict__ out)
{
    extern __shared__ float smem[];
    float* vt    = smem;                       // [TILE][258]
    float* tsum  = smem + TILE * 258;
    float* sfrac = tsum + TILE;
    float* mcs   = sfrac + TILE;
    float* msn   = mcs + TILE;
    int*   sidx0 = (int*)(msn + TILE);

    const int tid = threadIdx.x;
    const int b   = blockIdx.y;
    const int t0  = blockIdx.x * TILE;

    const float wl = fminf(fmaxf(wlp[0], 12.8f), 256.0f);
    const float st = fminf(fmaxf(stp[0], 0.0f), 256.0f);
    const float p  = pwp[0];

    if (tid < TILE) {
        int t = t0 + tid;
        float fv = __fmul_rn((float)t, st);   // == fp32 cumsum (exact here)
        float fl = floorf(fv);
        float fc = __fsub_rn(fv, fl);
        sfrac[tid] = fc;
        sidx0[tid] = (int)fl;
        float thm = __fmul_rn((float)(2.0 * M_PI / 256.0),
                              __fmul_rn(fc, 256.0f));
        mcs[tid] = cosf(thm);
        msn[tid] = sinf(thm);
    }
    __syncthreads();

    // ---- A1: hann taps (replica fp32 ops). 512 thr: col = tid&255, 32 frames each half.
    {
        const float hi  = ceilf (__fdiv_rn(__fadd_rn(255.0f, wl), 2.0f));
        const float lo  = floorf(__fdiv_rn(__fsub_rn(255.0f, wl), 2.0f));
        const float off = __fdiv_rn(__fadd_rn(__fsub_rn(wl, 256.0f), 1.0f), 2.0f);
        const float twopi = (float)(2.0 * M_PI);
        int col  = tid & 255;
        int kbeg = (tid >> 8) * 32;
        for (int k = kbeg; k < kbeg + 32; ++k) {
            float base = __fsub_rn((float)col, sfrac[k]);
            float arg  = __fdiv_rn(__fmul_rn(twopi, __fadd_rn(base, off)), wl);
            float tap  = __fsub_rn(0.5f, __fmul_rn(0.5f, cosf(arg)));
            if (base >= hi) tap = 0.0f;
            if (base <= lo) tap = 0.0f;
            vt[k * 258 + col] = tap;
        }
    }
    __syncthreads();

    // ---- A2: per-frame tap sums (identical per-frame summation pattern as R8/R9) ----
    {
        int w = tid >> 5, lane = tid & 31;   // 16 warps
        for (int k0 = 0; k0 < TILE; k0 += 16) {
            int k = k0 + w;
            float s = 0.0f;
            #pragma unroll
            for (int j = 0; j < 256; j += 32) s += vt[k * 258 + j + lane];
            #pragma unroll
            for (int o = 16; o > 0; o >>= 1) s += __shfl_down_sync(0xffffffffu, s, o);
            if (lane == 0) tsum[k] = s;
        }
    }
    __syncthreads();

    // ---- A3: tapered = x_gather * (tap / sum) [^p] ----
    {
        const float* xb = x + (size_t)b * LL;
        int col  = tid & 255;
        int kbeg = (tid >> 8) * 32;
        for (int k = kbeg; k < kbeg + 32; ++k) {
            int t = t0 + k;
            float v = 0.0f;
            if (t < TT) {
                int gi = sidx0[k] + col;
                float xv = (gi >= 0 && gi < LL) ? xb[gi] : 0.0f;
                float tapn = __fdiv_rn(vt[k * 258 + col], tsum[k]);
                if (p != 1.0f) tapn = powf(tapn, p);
                v = __fmul_rn(xv, tapn);
            }
            vt[k * 258 + col] = v;
        }
    }
    __syncthreads();

    // ---- B: direct DFT. Thread owns 2 frames (fr, fr+32) x 9 f-slots. ----
    const int fr    = tid & 31;            // lanes = frames -> coalesced stores
    const int fslot = (tid >> 5) & 15;     // warp-uniform -> coeff LDG broadcast

    unsigned long long acc[18];
    #pragma unroll
    for (int i = 0; i < 18; ++i) acc[i] = 0ull;

    const char* cbase = (const char*)(g_coeff + fslot * 256);

    ulonglong2 c_cur[9], c_nxt[9];
    #pragma unroll
    for (int i = 0; i < 9; ++i)
        c_cur[i] = __ldg((const ulonglong2*)(cbase + i * 32768));

    #pragma unroll 2
    for (int n = 0; n < 256; n += 2) {
        // prefetch next n-pair's coeffs while computing current
        if (n < 254) {
            const char* cp = cbase + (n + 2) * 8;
            #pragma unroll
            for (int i = 0; i < 9; ++i)
                c_nxt[i] = __ldg((const ulonglong2*)(cp + i * 32768));
        }
        float2 v0 = *(const float2*)&vt[fr * 258 + n];
        float2 v1 = *(const float2*)&vt[(fr + 32) * 258 + n];
        unsigned long long a00 = pk2(v0.x, v0.x);
        unsigned long long a01 = pk2(v0.y, v0.y);
        unsigned long long a10 = pk2(v1.x, v1.x);
        unsigned long long a11 = pk2(v1.y, v1.y);
        #pragma unroll
        for (int i = 0; i < 9; ++i) {
            fma2(acc[i],     a00, c_cur[i].x);
            fma2(acc[i],     a01, c_cur[i].y);
            fma2(acc[9 + i], a10, c_cur[i].x);
            fma2(acc[9 + i], a11, c_cur[i].y);
        }
        #pragma unroll
        for (int i = 0; i < 9; ++i) c_cur[i] = c_nxt[i];
    }

    // ---- C: sub-sample shift + outputs ----
    const float c2 = (float)(2.0 * M_PI / 256.0);
    #pragma unroll
    for (int i = 0; i < 9; ++i) {
        int f = fslot + 16 * i;
        if (f > 128) continue;
        #pragma unroll
        for (int j = 0; j < 2; ++j) {
            int frame = fr + 32 * j;
            int t = t0 + frame;
            if (t >= TT) continue;
            float Xr, Xi;
            upk2(acc[9 * j + i], Xr, Xi);

            float frac = sfrac[frame];
            float th = __fmul_rn(c2, __fmul_rn(frac, (float)f));
            float shc = cosf(th), shs = sinf(th);
            float Xr2 = __fsub_rn(__fmul_rn(Xr, shc), __fmul_rn(Xi, shs));
            float Xi2 = __fadd_rn(__fmul_rn(Xr, shs), __fmul_rn(Xi, shc));

            float spec = sqrtf(__fmaf_rn(Xr2, Xr2, __fmul_rn(Xi2, Xi2))) + 1.1920929e-7f;
            float ph   = atan2f(Xi2, Xr2);

            size_t ibf = ((size_t)b * FF + f) * TT + t;
            size_t ib  = ((size_t)b * NN + f) * TT + t;
            out[O_SPEC  + ibf] = spec;
            out[O_PHASE + ibf] = ph;
            out[O_STFT  + ib ] = Xr2;
            out[O_REAL  + ib ] = Xr2;
            out[O_IMAG  + ib ] = Xi2;

            if (f >= 1 && f <= 127) {
                float cp2 = mcs[frame], sp2 = msn[frame];
                float Xr3 = cp2 * Xr2 + sp2 * Xi2;   // e^{2pi i frac} * conj(X)
                float Xi3 = sp2 * Xr2 - cp2 * Xi2;
                size_t ib2 = ((size_t)b * NN + (NN - f)) * TT + t;
                out[O_STFT + ib2] = Xr3;
                out[O_REAL + ib2] = Xr3;
                out[O_IMAG + ib2] = Xi3;
            }
        }
    }
}

extern "C" void kernel_launch(void* const* d_in, const int* in_sizes, int n_in,
                              void* d_out, int out_size) {
    const float* x  = (const float*)d_in[0];
    const float* wl = (const float*)d_in[1];
    const float* st = (const float*)d_in[2];
    const float* pw = (const float*)d_in[3];
    float* out = (float*)d_out;

    build_coeff<<<(CROWS * NN + 255) / 256, 256>>>();

    const int smemBytes = (TILE * 258 + TILE * 5) * 4;   // ~67.3 KB
    static int attrSet = 0;
    if (!attrSet) {
        cudaFuncSetAttribute(dstft_main,
                             cudaFuncAttributeMaxDynamicSharedMemorySize,
                             smemBytes);
        attrSet = 1;
    }

    dim3 grid(NBLK, BB);
    dstft_main<<<grid, NTHR, smemBytes>>>(x, wl, st, pw, out);
}

// round 11
// speedup vs baseline: 1.2042x; 1.2042x over previous
#include <cuda_runtime.h>
#include <math.h>
#include <stdint.h>

#define NN   256
#define TT   16383
#define BB   8
#define LL   2097152
#define FF   129
#define TILE 64
#define NTHR 256
#define NBLK ((TT + TILE - 1) / TILE)   // 256

#define NC    16                        // n-samples per chunk
#define NCH   (NN / NC)                 // 16 chunks
#define CROWS 144                       // coeff rows (129 real + padding)
#define SC_U2_PER_BUF (CROWS * (NC / 2))   // 1152 ulonglong2 per buffer
#define SC_BYTES (2 * SC_U2_PER_BUF * 16)  // 36864

#define BFT ((size_t)BB * FF * TT)
#define BNT ((size_t)BB * NN * TT)
#define O_SPEC  ((size_t)0)
#define O_STFT  (BFT)
#define O_REAL  (BFT + BNT)
#define O_IMAG  (BFT + 2*BNT)
#define O_PHASE (BFT + 3*BNT)

__device__ __align__(16) float2 g_coeff[CROWS * NN];   // 294 KB

__device__ __forceinline__ unsigned long long pk2(float x, float y) {
    unsigned long long r;
    asm("mov.b64 %0, {%1,%2};" : "=l"(r) : "f"(x), "f"(y));
    return r;
}
__device__ __forceinline__ void upk2(unsigned long long v, float& x, float& y) {
    asm("mov.b64 {%0,%1}, %2;" : "=f"(x), "=f"(y) : "l"(v));
}
__device__ __forceinline__ void fma2(unsigned long long& d,
                                     unsigned long long a, unsigned long long b) {
    asm("fma.rn.f32x2 %0, %1, %2, %0;" : "+l"(d) : "l"(a), "l"(b));
}
__device__ __forceinline__ uint32_t smem_u32(const void* p) {
    uint32_t a;
    asm("{ .reg .u64 t; cvta.to.shared.u64 t, %1; cvt.u32.u64 %0, t; }"
        : "=r"(a) : "l"(p));
    return a;
}
__device__ __forceinline__ void cp_async16(uint32_t dst, const void* src) {
    asm volatile("cp.async.cg.shared.global [%0], [%1], 16;\n"
                 :: "r"(dst), "l"(src));
}

// Replica of reference coeff: exp((-2i*pi/256)*(f*n)); angle = fl32(c32*(f*n)),
// cos/sin via libdevice cosf/sinf (bit-identical to XLA:GPU's jnp.exp lowering).
__global__ void build_coeff() {
    int idx = blockIdx.x * 256 + threadIdx.x;
    if (idx >= CROWS * NN) return;
    int f = idx >> 8, n = idx & 255;
    const float c32 = (float)(-2.0 * M_PI / 256.0);
    float m  = (float)(f * n);
    float th = __fmul_rn(c32, m);
    g_coeff[idx] = make_float2(cosf(th), sinf(th));
}

__global__ __launch_bounds__(NTHR, 2)
void dstft_main(const float* __restrict__ x,
                const float* __restrict__ wlp,
                const float* __restrict__ stp,
                const float* __restrict__ pwp,
                float* __restrict__ out)
{
    extern __shared__ __align__(16) char smraw[];
    ulonglong2* sc = (ulonglong2*)smraw;                 // [2][1152]
    float* vt    = (float*)(smraw + SC_BYTES);           // [TILE][258]
    float* tsum  = vt + TILE * 258;
    float* sfrac = tsum + TILE;
    float* mcs   = sfrac + TILE;
    float* msn   = mcs + TILE;
    int*   sidx0 = (int*)(msn + TILE);

    const int tid = threadIdx.x;
    const int b   = blockIdx.y;
    const int t0  = blockIdx.x * TILE;

    const float wl = fminf(fmaxf(wlp[0], 12.8f), 256.0f);
    const float st = fminf(fmaxf(stp[0], 0.0f), 256.0f);
    const float p  = pwp[0];

    const uint32_t sc_u32 = smem_u32(sc);

    if (tid < TILE) {
        int t = t0 + tid;
        float fv = __fmul_rn((float)t, st);   // == fp32 cumsum (exact here)
        float fl = floorf(fv);
        float fc = __fsub_rn(fv, fl);
        sfrac[tid] = fc;
        sidx0[tid] = (int)fl;
        float thm = __fmul_rn((float)(2.0 * M_PI / 256.0),
                              __fmul_rn(fc, 256.0f));
        mcs[tid] = cosf(thm);
        msn[tid] = sinf(thm);
    }
    __syncthreads();

    // ---- A1: hann taps (replica fp32 ops) ----
    {
        const float hi  = ceilf (__fdiv_rn(__fadd_rn(255.0f, wl), 2.0f));
        const float lo  = floorf(__fdiv_rn(__fsub_rn(255.0f, wl), 2.0f));
        const float off = __fdiv_rn(__fadd_rn(__fsub_rn(wl, 256.0f), 1.0f), 2.0f);
        const float twopi = (float)(2.0 * M_PI);
        for (int k = 0; k < TILE; ++k) {
            float base = __fsub_rn((float)tid, sfrac[k]);
            float arg  = __fdiv_rn(__fmul_rn(twopi, __fadd_rn(base, off)), wl);
            float tap  = __fsub_rn(0.5f, __fmul_rn(0.5f, cosf(arg)));
            if (base >= hi) tap = 0.0f;
            if (base <= lo) tap = 0.0f;
            vt[k * 258 + tid] = tap;
        }
    }
    __syncthreads();

    // ---- A2: per-frame tap sums (same order as R8/R9) ----
    {
        int w = tid >> 5, lane = tid & 31;
        for (int k0 = 0; k0 < TILE; k0 += 8) {
            int k = k0 + w;
            float s = 0.0f;
            #pragma unroll
            for (int j = 0; j < 256; j += 32) s += vt[k * 258 + j + lane];
            #pragma unroll
            for (int o = 16; o > 0; o >>= 1) s += __shfl_down_sync(0xffffffffu, s, o);
            if (lane == 0) tsum[k] = s;
        }
    }
    __syncthreads();

    // ---- A3: tapered = x_gather * (tap / sum) [^p] ----
    {
        const float* xb = x + (size_t)b * LL;
        for (int k = 0; k < TILE; ++k) {
            int t = t0 + k;
            float v = 0.0f;
            if (t < TT) {
                int gi = sidx0[k] + tid;
                float xv = (gi >= 0 && gi < LL) ? xb[gi] : 0.0f;
                float tapn = __fdiv_rn(vt[k * 258 + tid], tsum[k]);
                if (p != 1.0f) tapn = powf(tapn, p);
                v = __fmul_rn(xv, tapn);
            }
            vt[k * 258 + tid] = v;
        }
    }
    __syncthreads();

    // ---- B: chunked DFT; coeff chunks staged via cp.async double buffer ----
    const int fr    = tid & 15;     // frame group: frames fr + 16j
    const int fslot = tid >> 4;     // f = fslot + 16i

    unsigned long long acc[36];
    #pragma unroll
    for (int i = 0; i < 36; ++i) acc[i] = 0ull;

    // issue chunk 0
    {
        int n0 = 0;
        for (int j = tid; j < SC_U2_PER_BUF; j += NTHR) {
            int row = j >> 3, pair = j & 7;
            const float2* src = g_coeff + row * 256 + n0 + pair * 2;
            cp_async16(sc_u32 + (uint32_t)j * 16, src);
        }
        asm volatile("cp.async.commit_group;" ::: "memory");
    }

    for (int c = 0; c < NCH; ++c) {
        asm volatile("cp.async.wait_group 0;" ::: "memory");
        __syncthreads();   // chunk c visible; prev compute done (buffer reuse safe)

        if (c + 1 < NCH) {
            int n0 = (c + 1) * NC;
            uint32_t dbase = sc_u32 + (uint32_t)(((c + 1) & 1) * SC_U2_PER_BUF) * 16;
            for (int j = tid; j < SC_U2_PER_BUF; j += NTHR) {
                int row = j >> 3, pair = j & 7;
                const float2* src = g_coeff + row * 256 + n0 + pair * 2;
                cp_async16(dbase + (uint32_t)j * 16, src);
            }
            asm volatile("cp.async.commit_group;" ::: "memory");
        }

        const ulonglong2* scp = sc + (c & 1) * SC_U2_PER_BUF;
        const int nbase = c * NC;
        #pragma unroll
        for (int np = 0; np < NC / 2; ++np) {
            int n = nbase + np * 2;
            unsigned long long a0[4], a1[4];
            #pragma unroll
            for (int j = 0; j < 4; ++j) {
                float2 vv = *(const float2*)&vt[(fr + 16 * j) * 258 + n];
                a0[j] = pk2(vv.x, vv.x);
                a1[j] = pk2(vv.y, vv.y);
            }
            #pragma unroll
            for (int i = 0; i < 9; ++i) {
                ulonglong2 cc = scp[(fslot + 16 * i) * (NC / 2) + np];
                #pragma unroll
                for (int j = 0; j < 4; ++j) {
                    fma2(acc[i * 4 + j], a0[j], cc.x);
                    fma2(acc[i * 4 + j], a1[j], cc.y);
                }
            }
        }
        __syncthreads();   // compute c done before buffer (c&1) is refilled at c+2
    }

    // ---- C: sub-sample shift + outputs ----
    const float c2 = (float)(2.0 * M_PI / 256.0);
    #pragma unroll
    for (int i = 0; i < 9; ++i) {
        int f = fslot + 16 * i;
        if (f > 128) continue;
        #pragma unroll
        for (int j = 0; j < 4; ++j) {
            int frame = fr + 16 * j;
            int t = t0 + frame;
            if (t >= TT) continue;
            float Xr, Xi;
            upk2(acc[i * 4 + j], Xr, Xi);

            float frac = sfrac[frame];
            float th = __fmul_rn(c2, __fmul_rn(frac, (float)f));
            float shc = cosf(th), shs = sinf(th);
            float Xr2 = __fsub_rn(__fmul_rn(Xr, shc), __fmul_rn(Xi, shs));
            float Xi2 = __fadd_rn(__fmul_rn(Xr, shs), __fmul_rn(Xi, shc));

            float spec = sqrtf(__fmaf_rn(Xr2, Xr2, __fmul_rn(Xi2, Xi2))) + 1.1920929e-7f;
            float ph   = atan2f(Xi2, Xr2);

            size_t ibf = ((size_t)b * FF + f) * TT + t;
            size_t ib  = ((size_t)b * NN + f) * TT + t;
            out[O_SPEC  + ibf] = spec;
            out[O_PHASE + ibf] = ph;
            out[O_STFT  + ib ] = Xr2;
            out[O_REAL  + ib ] = Xr2;
            out[O_IMAG  + ib ] = Xi2;

            if (f >= 1 && f <= 127) {
                float cp2 = mcs[frame], sp2 = msn[frame];
                float Xr3 = cp2 * Xr2 + sp2 * Xi2;   // e^{2pi i frac} * conj(X)
                float Xi3 = sp2 * Xr2 - cp2 * Xi2;
                size_t ib2 = ((size_t)b * NN + (NN - f)) * TT + t;
                out[O_STFT + ib2] = Xr3;
                out[O_REAL + ib2] = Xr3;
                out[O_IMAG + ib2] = Xi3;
            }
        }
    }
}

extern "C" void kernel_launch(void* const* d_in, const int* in_sizes, int n_in,
                              void* d_out, int out_size) {
    const float* x  = (const float*)d_in[0];
    const float* wl = (const float*)d_in[1];
    const float* st = (const float*)d_in[2];
    const float* pw = (const float*)d_in[3];
    float* out = (float*)d_out;

    build_coeff<<<(CROWS * NN + 255) / 256, 256>>>();

    const int smemBytes = SC_BYTES + (TILE * 258 + TILE * 5) * 4;   // ~104 KB
    static int attrSet = 0;
    if (!attrSet) {
        cudaFuncSetAttribute(dstft_main,
                             cudaFuncAttributeMaxDynamicSharedMemorySize,
                             smemBytes);
        attrSet = 1;
    }

    dim3 grid(NBLK, BB);
    dstft_main<<<grid, NTHR, smemBytes>>>(x, wl, st, pw, out);
}

// round 12
// speedup vs baseline: 1.5710x; 1.3046x over previous
#include <cuda_runtime.h>
#include <math.h>
#include <stdint.h>

#define NN   256
#define TT   16383
#define BB   8
#define LL   2097152
#define FF   129
#define TILE 32
#define NTHR 256
#define NBLK ((TT + TILE - 1) / TILE)   // 512

#define NC    16                        // n-samples per chunk
#define NCH   (NN / NC)                 // 16 chunks
#define CROWS 144                       // coeff rows (129 real + padding)
#define SC_U2_PER_BUF (CROWS * (NC / 2))   // 1152 ulonglong2 per buffer
#define SC_BYTES (2 * SC_U2_PER_BUF * 16)  // 36864

#define BFT ((size_t)BB * FF * TT)
#define BNT ((size_t)BB * NN * TT)
#define O_SPEC  ((size_t)0)
#define O_STFT  (BFT)
#define O_REAL  (BFT + BNT)
#define O_IMAG  (BFT + 2*BNT)
#define O_PHASE (BFT + 3*BNT)

__device__ __align__(16) float2 g_coeff[CROWS * NN];   // 294 KB

__device__ __forceinline__ unsigned long long pk2(float x, float y) {
    unsigned long long r;
    asm("mov.b64 %0, {%1,%2};" : "=l"(r) : "f"(x), "f"(y));
    return r;
}
__device__ __forceinline__ void upk2(unsigned long long v, float& x, float& y) {
    asm("mov.b64 {%0,%1}, %2;" : "=f"(x), "=f"(y) : "l"(v));
}
__device__ __forceinline__ void fma2(unsigned long long& d,
                                     unsigned long long a, unsigned long long b) {
    asm("fma.rn.f32x2 %0, %1, %2, %0;" : "+l"(d) : "l"(a), "l"(b));
}
__device__ __forceinline__ uint32_t smem_u32(const void* p) {
    uint32_t a;
    asm("{ .reg .u64 t; cvta.to.shared.u64 t, %1; cvt.u32.u64 %0, t; }"
        : "=r"(a) : "l"(p));
    return a;
}
__device__ __forceinline__ void cp_async16(uint32_t dst, const void* src) {
    asm volatile("cp.async.cg.shared.global [%0], [%1], 16;\n"
                 :: "r"(dst), "l"(src));
}

// Replica of reference coeff: exp((-2i*pi/256)*(f*n)); angle = fl32(c32*(f*n)),
// cos/sin via libdevice cosf/sinf (bit-identical to XLA:GPU's jnp.exp lowering).
__global__ void build_coeff() {
    int idx = blockIdx.x * 256 + threadIdx.x;
    if (idx >= CROWS * NN) return;
    int f = idx >> 8, n = idx & 255;
    const float c32 = (float)(-2.0 * M_PI / 256.0);
    float m  = (float)(f * n);
    float th = __fmul_rn(c32, m);
    g_coeff[idx] = make_float2(cosf(th), sinf(th));
}

__device__ __forceinline__ void issue_chunk(uint32_t sc_u32, int chunk, int tid) {
    int n0 = chunk * NC;
    uint32_t dbase = sc_u32 + (uint32_t)((chunk & 1) * SC_U2_PER_BUF) * 16;
    for (int j = tid; j < SC_U2_PER_BUF; j += NTHR) {
        int row = j >> 3, pair = j & 7;
        const float2* src = g_coeff + row * 256 + n0 + pair * 2;
        cp_async16(dbase + (uint32_t)j * 16, src);
    }
    asm volatile("cp.async.commit_group;" ::: "memory");
}

__global__ __launch_bounds__(NTHR, 3)
void dstft_main(const float* __restrict__ x,
                const float* __restrict__ wlp,
                const float* __restrict__ stp,
                const float* __restrict__ pwp,
                float* __restrict__ out)
{
    extern __shared__ __align__(16) char smraw[];
    ulonglong2* sc = (ulonglong2*)smraw;                 // [2][1152]
    float* vt    = (float*)(smraw + SC_BYTES);           // [TILE][258]
    float* tsum  = vt + TILE * 258;
    float* sfrac = tsum + TILE;
    float* mcs   = sfrac + TILE;
    float* msn   = mcs + TILE;
    int*   sidx0 = (int*)(msn + TILE);

    const int tid = threadIdx.x;
    const int b   = blockIdx.y;
    const int t0  = blockIdx.x * TILE;

    const float wl = fminf(fmaxf(wlp[0], 12.8f), 256.0f);
    const float st = fminf(fmaxf(stp[0], 0.0f), 256.0f);
    const float p  = pwp[0];

    const uint32_t sc_u32 = smem_u32(sc);

    // Prefetch coeff chunk 0 immediately; overlaps with tap phases below.
    issue_chunk(sc_u32, 0, tid);

    if (tid < TILE) {
        int t = t0 + tid;
        float fv = __fmul_rn((float)t, st);   // == fp32 cumsum (exact here)
        float fl = floorf(fv);
        float fc = __fsub_rn(fv, fl);
        sfrac[tid] = fc;
        sidx0[tid] = (int)fl;
        float thm = __fmul_rn((float)(2.0 * M_PI / 256.0),
                              __fmul_rn(fc, 256.0f));
        mcs[tid] = cosf(thm);
        msn[tid] = sinf(thm);
    }
    __syncthreads();

    // ---- A1: hann taps (replica fp32 ops) ----
    {
        const float hi  = ceilf (__fdiv_rn(__fadd_rn(255.0f, wl), 2.0f));
        const float lo  = floorf(__fdiv_rn(__fsub_rn(255.0f, wl), 2.0f));
        const float off = __fdiv_rn(__fadd_rn(__fsub_rn(wl, 256.0f), 1.0f), 2.0f);
        const float twopi = (float)(2.0 * M_PI);
        for (int k = 0; k < TILE; ++k) {
            float base = __fsub_rn((float)tid, sfrac[k]);
            float arg  = __fdiv_rn(__fmul_rn(twopi, __fadd_rn(base, off)), wl);
            float tap  = __fsub_rn(0.5f, __fmul_rn(0.5f, cosf(arg)));
            if (base >= hi) tap = 0.0f;
            if (base <= lo) tap = 0.0f;
            vt[k * 258 + tid] = tap;
        }
    }
    __syncthreads();

    // ---- A2: per-frame tap sums (same order as R8-R11) ----
    {
        int w = tid >> 5, lane = tid & 31;
        for (int k0 = 0; k0 < TILE; k0 += 8) {
            int k = k0 + w;
            float s = 0.0f;
            #pragma unroll
            for (int j = 0; j < 256; j += 32) s += vt[k * 258 + j + lane];
            #pragma unroll
            for (int o = 16; o > 0; o >>= 1) s += __shfl_down_sync(0xffffffffu, s, o);
            if (lane == 0) tsum[k] = s;
        }
    }
    __syncthreads();

    // ---- A3: tapered = x_gather * (tap / sum) [^p] ----
    {
        const float* xb = x + (size_t)b * LL;
        for (int k = 0; k < TILE; ++k) {
            int t = t0 + k;
            float v = 0.0f;
            if (t < TT) {
                int gi = sidx0[k] + tid;
                float xv = (gi >= 0 && gi < LL) ? xb[gi] : 0.0f;
                float tapn = __fdiv_rn(vt[k * 258 + tid], tsum[k]);
                if (p != 1.0f) tapn = powf(tapn, p);
                v = __fmul_rn(xv, tapn);
            }
            vt[k * 258 + tid] = v;
        }
    }
    __syncthreads();

    // ---- B: chunked DFT; thread tile = 9 f-slots x 2 frames ----
    const int fr    = tid & 15;     // frames fr, fr+16
    const int fslot = tid >> 4;     // f = fslot + 16i

    unsigned long long acc[18];
    #pragma unroll
    for (int i = 0; i < 18; ++i) acc[i] = 0ull;

    #pragma unroll 1
    for (int c = 0; c < NCH; ++c) {
        if (c + 1 < NCH) issue_chunk(sc_u32, c + 1, tid);
        if (c + 1 < NCH) {
            asm volatile("cp.async.wait_group 1;" ::: "memory");  // chunk c done
        } else {
            asm volatile("cp.async.wait_group 0;" ::: "memory");  // last chunk
        }
        __syncthreads();

        const ulonglong2* scp = sc + (c & 1) * SC_U2_PER_BUF;
        const int nbase = c * NC;
        #pragma unroll
        for (int np = 0; np < NC / 2; ++np) {
            int n = nbase + np * 2;
            float2 v0 = *(const float2*)&vt[fr * 258 + n];
            float2 v1 = *(const float2*)&vt[(fr + 16) * 258 + n];
            unsigned long long a00 = pk2(v0.x, v0.x);
            unsigned long long a01 = pk2(v0.y, v0.y);
            unsigned long long a10 = pk2(v1.x, v1.x);
            unsigned long long a11 = pk2(v1.y, v1.y);
            #pragma unroll
            for (int i = 0; i < 9; ++i) {
                ulonglong2 cc = scp[(fslot + 16 * i) * (NC / 2) + np];
                fma2(acc[i],     a00, cc.x);
                fma2(acc[i],     a01, cc.y);
                fma2(acc[9 + i], a10, cc.x);
                fma2(acc[9 + i], a11, cc.y);
            }
        }
        __syncthreads();   // compute on buffer done before it is refilled
    }

    // ---- C: sub-sample shift + outputs ----
    const float c2 = (float)(2.0 * M_PI / 256.0);
    #pragma unroll
    for (int i = 0; i < 9; ++i) {
        int f = fslot + 16 * i;
        if (f > 128) continue;
        #pragma unroll
        for (int j = 0; j < 2; ++j) {
            int frame = fr + 16 * j;
            int t = t0 + frame;
            if (t >= TT) continue;
            float Xr, Xi;
            upk2(acc[9 * j + i], Xr, Xi);

            float frac = sfrac[frame];
            float th = __fmul_rn(c2, __fmul_rn(frac, (float)f));
            float shc = cosf(th), shs = sinf(th);
            float Xr2 = __fsub_rn(__fmul_rn(Xr, shc), __fmul_rn(Xi, shs));
            float Xi2 = __fadd_rn(__fmul_rn(Xr, shs), __fmul_rn(Xi, shc));

            float spec = sqrtf(__fmaf_rn(Xr2, Xr2, __fmul_rn(Xi2, Xi2))) + 1.1920929e-7f;
            float ph   = atan2f(Xi2, Xr2);

            size_t ibf = ((size_t)b * FF + f) * TT + t;
            size_t ib  = ((size_t)b * NN + f) * TT + t;
            out[O_SPEC  + ibf] = spec;
            out[O_PHASE + ibf] = ph;
            out[O_STFT  + ib ] = Xr2;
            out[O_REAL  + ib ] = Xr2;
            out[O_IMAG  + ib ] = Xi2;

            if (f >= 1 && f <= 127) {
                float cp2 = mcs[frame], sp2 = msn[frame];
                float Xr3 = cp2 * Xr2 + sp2 * Xi2;   // e^{2pi i frac} * conj(X)
                float Xi3 = sp2 * Xr2 - cp2 * Xi2;
                size_t ib2 = ((size_t)b * NN + (NN - f)) * TT + t;
                out[O_STFT + ib2] = Xr3;
                out[O_REAL + ib2] = Xr3;
                out[O_IMAG + ib2] = Xi3;
            }
        }
    }
}

extern "C" void kernel_launch(void* const* d_in, const int* in_sizes, int n_in,
                              void* d_out, int out_size) {
    const float* x  = (const float*)d_in[0];
    const float* wl = (const float*)d_in[1];
    const float* st = (const float*)d_in[2];
    const float* pw = (const float*)d_in[3];
    float* out = (float*)d_out;

    build_coeff<<<(CROWS * NN + 255) / 256, 256>>>();

    const int smemBytes = SC_BYTES + (TILE * 258 + TILE * 5) * 4;   // ~70.6 KB
    static int attrSet = 0;
    if (!attrSet) {
        cudaFuncSetAttribute(dstft_main,
                             cudaFuncAttributeMaxDynamicSharedMemorySize,
                             smemBytes);
        attrSet = 1;
    }

    dim3 grid(NBLK, BB);
    dstft_main<<<grid, NTHR, smemBytes>>>(x, wl, st, pw, out);
}